// round 5
// baseline (speedup 1.0000x reference)
#include <cuda_runtime.h>
#include <cstdint>

#define BATCH 32768
#define IDIM  128
#define HDIM  256
#define ADIM  32
#define MT    128
#define NT    512
#define NBLK  (BATCH/MT)
#define NC    64

#define A_FLOATS 4096                 // 8 mb * 4 g * 128
#define W_FLOATS 6144                 // 24 nb-blk * 4 g * 64
#define BUF_SZ   (A_FLOATS + W_FLOATS)
#define SMEM_DYN (2*BUF_SZ*4)         // 81920 B

// tf32-preconverted weights: wih0 | whh0 | wih1 | whh1
#define W0_OFF 0
#define W1_OFF 98304
#define W2_OFF 294912
#define W3_OFF 491520
#define WSCR_TOTAL 688128
__device__ float w_scr[WSCR_TOTAL];

static __device__ __forceinline__ float tf32r(float x) {
    float r; asm("cvt.rna.tf32.f32 %0, %1;" : "=f"(r) : "f"(x)); return r;
}
static __device__ __forceinline__ void mma8(float c[4], const uint32_t a[4],
                                            const uint32_t b[2]) {
    asm volatile(
        "mma.sync.aligned.m16n8k8.row.col.f32.tf32.tf32.f32 "
        "{%0,%1,%2,%3},{%4,%5,%6,%7},{%8,%9},{%0,%1,%2,%3};"
        : "+f"(c[0]), "+f"(c[1]), "+f"(c[2]), "+f"(c[3])
        : "r"(a[0]), "r"(a[1]), "r"(a[2]), "r"(a[3]), "r"(b[0]), "r"(b[1]));
}
static __device__ __forceinline__ float sigf(float x) {
    return __fdividef(1.0f, 1.0f + __expf(-x));
}
static __device__ __forceinline__ float tanhff(float x) {
    float ax = fabsf(x), e = __expf(-2.0f * ax);
    return copysignf(__fdividef(1.0f - e, 1.0f + e), x);
}
static __device__ __forceinline__ float gru1(float rp, float zp, float ip,
                                             float hp, float hv) {
    float r = sigf(rp), z = sigf(zp);
    float n = tanhff(ip + r * hp);
    return n + z * (hv - n);
}

__global__ void __launch_bounds__(256)
cvt_weights_kernel(const float* __restrict__ wih0, const float* __restrict__ whh0,
                   const float* __restrict__ wih1, const float* __restrict__ whh1)
{
    int i = blockIdx.x * 256 + threadIdx.x;          // float4 index
    if (i >= WSCR_TOTAL / 4) return;
    const float* src;
    int j = i * 4;
    if      (j < W1_OFF) src = wih0 + j;
    else if (j < W2_OFF) src = whh0 + (j - W1_OFF);
    else if (j < W3_OFF) src = wih1 + (j - W2_OFF);
    else                 src = whh1 + (j - W3_OFF);
    float4 v = *(const float4*)src;
    v.x = tf32r(v.x); v.y = tf32r(v.y); v.z = tf32r(v.z); v.w = tf32r(v.w);
    *(float4*)(w_scr + j) = v;
}

__global__ void __launch_bounds__(NT, 1)
gru_ac_kernel(const float* __restrict__ x,    const float* __restrict__ hin,
              const float* __restrict__ bih0, const float* __restrict__ bhh0,
              const float* __restrict__ bih1, const float* __restrict__ bhh1,
              const float* __restrict__ wp,   const float* __restrict__ bp,
              const float* __restrict__ wv,   const float* __restrict__ bv,
              float* __restrict__ out)
{
    extern __shared__ float sm[];
    const int tid  = threadIdx.x;
    const int lane = tid & 31;
    const int wid  = tid >> 5;
    const int wm   = wid >> 2;     // 0..3
    const int wn   = wid & 3;      // 0..3
    const int gID  = lane >> 2;
    const int tig  = lane & 3;
    const int rowbase = blockIdx.x * MT;

    float* outL  = out;
    float* outV  = out + (size_t)BATCH * ADIM;
    float* hbase = out + (size_t)BATCH * (ADIM + 1);   // [2][B][H]

    // --- staging geometry (fragment-packed smem layout) ---
    // A value A[r][k] (k in 0..31): block=(r>>4)*4+(k>>3), lane=(r&7... )
    int a_r[2], a_kq[2], a_off[2];
    #pragma unroll
    for (int i = 0; i < 2; ++i) {
        int idx = tid + i * NT;            // 0..1023 (float4 id)
        a_r[i]  = idx >> 3;                // row 0..127
        a_kq[i] = idx & 7;                 // k0 = kq*4
        int rr  = a_r[i] & 15;
        a_off[i] = (((a_r[i] >> 4) * 4 + (a_kq[i] >> 1)) << 7)
                 + ((rr & 7) << 4) + ((a_kq[i] & 1) << 1) + (rr >> 3);
    }
    int w_row[3], w_kq[3], w_off[3];
    #pragma unroll
    for (int i = 0; i < 3; ++i) {
        int idx = tid + i * NT;            // 0..1535
        w_row[i] = idx >> 3;               // 0..191 = gate*64 + nl
        w_kq[i]  = idx & 7;
        int gate = w_row[i] >> 6, nl = w_row[i] & 63;
        w_off[i] = (((gate * 8 + (nl >> 3)) * 4 + (w_kq[i] >> 1)) << 6)
                 + ((nl & 7) << 3) + (w_kq[i] & 1);
    }

    for (int layer = 0; layer < 2; ++layer) {
        const float* wih = w_scr + (layer ? W2_OFF : W0_OFF);
        const float* whh = w_scr + (layer ? W3_OFF : W1_OFF);
        const float* bih = layer ? bih1 : bih0;
        const float* bhh = layer ? bhh1 : bhh0;
        const int    KX  = layer ? HDIM : IDIM;
        const int    ncx = KX >> 5;
        const int    nk  = ncx + (HDIM >> 5);
        const float* asrcx = layer ? (hbase + (size_t)rowbase * HDIM)
                                   : (x + (size_t)rowbase * IDIM);
        const int    axs   = layer ? HDIM : IDIM;
        const float* asrch = hin + (size_t)layer * BATCH * HDIM
                                 + (size_t)rowbase * HDIM;
        float*       hdst  = hbase + (size_t)layer * BATCH * HDIM
                                   + (size_t)rowbase * HDIM;

        for (int q = 0; q < 4; ++q) {
            const int qc = q * NC;

            auto fetch = [&](int kc, float4 v[5]) {
                const bool isX = kc < ncx;
                const float* ab  = isX ? asrcx : asrch;
                const int    as_ = isX ? axs : HDIM;
                const float* wb  = isX ? wih : whh;
                const int    wk  = isX ? KX : HDIM;
                const int    ko  = (isX ? kc : kc - ncx) << 5;
                #pragma unroll
                for (int i = 0; i < 2; ++i)
                    v[i] = *(const float4*)(ab + (size_t)a_r[i] * as_
                                               + ko + a_kq[i] * 4);
                #pragma unroll
                for (int i = 0; i < 3; ++i) {
                    int gate = w_row[i] >> 6, nl = w_row[i] & 63;
                    v[2 + i] = *(const float4*)(wb
                        + (size_t)(gate * 256 + qc + nl) * wk + ko + w_kq[i] * 4);
                }
            };
            auto store = [&](int buf, const float4 v[5]) {
                float* Ab = sm + buf * BUF_SZ;
                float* Wb = Ab + A_FLOATS;
                #pragma unroll
                for (int i = 0; i < 2; ++i) {
                    float* b = Ab + a_off[i];
                    b[0] = tf32r(v[i].x); b[4]  = tf32r(v[i].y);
                    b[8] = tf32r(v[i].z); b[12] = tf32r(v[i].w);
                }
                #pragma unroll
                for (int i = 0; i < 3; ++i) {
                    float* b = Wb + w_off[i];          // weights pre-converted
                    b[0] = v[2 + i].x; b[2] = v[2 + i].y;
                    b[4] = v[2 + i].z; b[6] = v[2 + i].w;
                }
            };

            float aR[2][2][4], aZ[2][2][4], aI[2][2][4], aH[2][2][4];
            #pragma unroll
            for (int t = 0; t < 2; ++t)
                #pragma unroll
                for (int s = 0; s < 2; ++s)
                    #pragma unroll
                    for (int k = 0; k < 4; ++k) {
                        aR[t][s][k] = 0.f; aZ[t][s][k] = 0.f;
                        aI[t][s][k] = 0.f; aH[t][s][k] = 0.f;
                    }

            { float4 v0[5]; fetch(0, v0); store(0, v0); }
            __syncthreads();

            for (int kc = 0; kc < nk; ++kc) {
                const bool hn = (kc + 1) < nk;
                float4 v[5];
                if (hn) fetch(kc + 1, v);

                const float* Ab = sm + (kc & 1) * BUF_SZ;
                const float* Wb = Ab + A_FLOATS;
                const bool isX = kc < ncx;

                #pragma unroll
                for (int g = 0; g < 4; ++g) {
                    uint32_t af[2][4];
                    #pragma unroll
                    for (int t = 0; t < 2; ++t) {
                        float4 av = *(const float4*)(Ab
                            + ((((wm * 2 + t) * 4 + g) << 7) + lane * 4));
                        af[t][0] = __float_as_uint(av.x);
                        af[t][1] = __float_as_uint(av.y);
                        af[t][2] = __float_as_uint(av.z);
                        af[t][3] = __float_as_uint(av.w);
                    }
                    #pragma unroll
                    for (int s = 0; s < 2; ++s) {
                        const int nbb = wn * 2 + s;
                        float2 r2 = *(const float2*)(Wb
                            + (((nbb)       * 4 + g) << 6) + lane * 2);
                        float2 z2 = *(const float2*)(Wb
                            + (((8 + nbb)   * 4 + g) << 6) + lane * 2);
                        float2 n2 = *(const float2*)(Wb
                            + (((16 + nbb)  * 4 + g) << 6) + lane * 2);
                        uint32_t bR[2] = { __float_as_uint(r2.x), __float_as_uint(r2.y) };
                        uint32_t bZ[2] = { __float_as_uint(z2.x), __float_as_uint(z2.y) };
                        uint32_t bN[2] = { __float_as_uint(n2.x), __float_as_uint(n2.y) };
                        #pragma unroll
                        for (int t = 0; t < 2; ++t) {
                            mma8(aR[t][s], af[t], bR);
                            mma8(aZ[t][s], af[t], bZ);
                        }
                        if (isX) {
                            #pragma unroll
                            for (int t = 0; t < 2; ++t) mma8(aI[t][s], af[t], bN);
                        } else {
                            #pragma unroll
                            for (int t = 0; t < 2; ++t) mma8(aH[t][s], af[t], bN);
                        }
                    }
                }
                if (hn) store((kc + 1) & 1, v);
                __syncthreads();
            }

            // elementwise GRU gates from fragments (biases fused from gmem)
            #pragma unroll
            for (int s = 0; s < 2; ++s) {
                const int c = qc + wn * 16 + s * 8 + tig * 2;
                float2 bi0 = *(const float2*)&bih[c];
                float2 bh0 = *(const float2*)&bhh[c];
                float2 bi1 = *(const float2*)&bih[256 + c];
                float2 bh1 = *(const float2*)&bhh[256 + c];
                float2 bIv = *(const float2*)&bih[512 + c];
                float2 bHv = *(const float2*)&bhh[512 + c];
                float2 bRv = make_float2(bi0.x + bh0.x, bi0.y + bh0.y);
                float2 bZv = make_float2(bi1.x + bh1.x, bi1.y + bh1.y);
                #pragma unroll
                for (int t = 0; t < 2; ++t) {
                    const int ra = wm * 32 + t * 16 + gID;
                    const int rb = ra + 8;
                    float2 ha = *(const float2*)&asrch[(size_t)ra * HDIM + c];
                    float2 hb = *(const float2*)&asrch[(size_t)rb * HDIM + c];
                    float2 oa, ob;
                    oa.x = gru1(aR[t][s][0] + bRv.x, aZ[t][s][0] + bZv.x,
                                aI[t][s][0] + bIv.x, aH[t][s][0] + bHv.x, ha.x);
                    oa.y = gru1(aR[t][s][1] + bRv.y, aZ[t][s][1] + bZv.y,
                                aI[t][s][1] + bIv.y, aH[t][s][1] + bHv.y, ha.y);
                    ob.x = gru1(aR[t][s][2] + bRv.x, aZ[t][s][2] + bZv.x,
                                aI[t][s][2] + bIv.x, aH[t][s][2] + bHv.x, hb.x);
                    ob.y = gru1(aR[t][s][3] + bRv.y, aZ[t][s][3] + bZv.y,
                                aI[t][s][3] + bIv.y, aH[t][s][3] + bHv.y, hb.y);
                    *(float2*)&hdst[(size_t)ra * HDIM + c] = oa;
                    *(float2*)&hdst[(size_t)rb * HDIM + c] = ob;
                }
            }
            __syncthreads();
        }
    }

    // heads: logits = h1 @ w_p^T + b_p ; value = h1 @ w_v^T + b_v
    {
        const int row = tid >> 2;              // 0..127
        const int qq  = tid & 3;
        const float* h1r = hbase + (size_t)BATCH * HDIM
                                 + (size_t)(rowbase + row) * HDIM;
        float acc[8];
        #pragma unroll
        for (int a = 0; a < 8; ++a) acc[a] = bp[qq * 8 + a];
        float av = bv[0];
        const float4* h4 = (const float4*)h1r;
        for (int kb = 0; kb < HDIM / 4; ++kb) {
            float4 hv = h4[kb];
            #pragma unroll
            for (int a = 0; a < 8; ++a) {
                const float4 wq =
                    *(const float4*)&wp[(qq * 8 + a) * HDIM + kb * 4];
                acc[a] += hv.x * wq.x + hv.y * wq.y + hv.z * wq.z + hv.w * wq.w;
            }
            if (qq == 0) {
                const float4 wq = *(const float4*)&wv[kb * 4];
                av += hv.x * wq.x + hv.y * wq.y + hv.z * wq.z + hv.w * wq.w;
            }
        }
        #pragma unroll
        for (int a = 0; a < 8; ++a)
            outL[(size_t)(rowbase + row) * ADIM + qq * 8 + a] = acc[a];
        if (qq == 0) outV[rowbase + row] = av;
    }
}

extern "C" void kernel_launch(void* const* d_in, const int* in_sizes, int n_in,
                              void* d_out, int out_size) {
    const float* x    = (const float*)d_in[0];
    const float* hin  = (const float*)d_in[1];
    const float* wih0 = (const float*)d_in[2];
    const float* whh0 = (const float*)d_in[3];
    const float* bih0 = (const float*)d_in[4];
    const float* bhh0 = (const float*)d_in[5];
    const float* wih1 = (const float*)d_in[6];
    const float* whh1 = (const float*)d_in[7];
    const float* bih1 = (const float*)d_in[8];
    const float* bhh1 = (const float*)d_in[9];
    const float* wp   = (const float*)d_in[10];
    const float* bp   = (const float*)d_in[11];
    const float* wv   = (const float*)d_in[12];
    const float* bv   = (const float*)d_in[13];
    float* out = (float*)d_out;

    cvt_weights_kernel<<<(WSCR_TOTAL / 4 + 255) / 256, 256>>>(wih0, whh0, wih1, whh1);

    cudaFuncSetAttribute(gru_ac_kernel,
                         cudaFuncAttributeMaxDynamicSharedMemorySize, SMEM_DYN);
    gru_ac_kernel<<<NBLK, NT, SMEM_DYN>>>(x, hin, bih0, bhh0, bih1, bhh1,
                                          wp, bp, wv, bv, out);
}

// round 6
// speedup vs baseline: 1.0641x; 1.0641x over previous
#include <cuda_runtime.h>
#include <cstdint>

#define BATCH 32768
#define IDIM  128
#define HDIM  256
#define ADIM  32
#define MT    128
#define NT    512
#define NBLK  (BATCH/MT)
#define NC    64

#define AST     36
#define ASM_SZ  (128*AST)              // 4608 floats
#define WSM_SZ  (192*AST)              // 6912 floats
#define BUF_SZ  (ASM_SZ+WSM_SZ)        // 11520 floats
#define BIAS_OFF (3*BUF_SZ)
#define SMEM_DYN ((3*BUF_SZ + 4*HDIM)*4)   // 142336 B

// tf32-preconverted weights: wih0 | whh0 | wih1 | whh1
#define W0_OFF 0
#define W1_OFF 98304
#define W2_OFF 294912
#define W3_OFF 491520
#define WSCR_TOTAL 688128
__device__ float w_scr[WSCR_TOTAL];

static __device__ __forceinline__ uint32_t smem_u32(const void* p) {
    uint32_t a;
    asm("{ .reg .u64 t; cvta.to.shared.u64 t, %1; cvt.u32.u64 %0, t; }"
        : "=r"(a) : "l"(p));
    return a;
}
static __device__ __forceinline__ float tf32r(float x) {
    float r; asm("cvt.rna.tf32.f32 %0, %1;" : "=f"(r) : "f"(x)); return r;
}
static __device__ __forceinline__ uint32_t lda(const float* p) {   // A: cvt+load
    return __float_as_uint(tf32r(*p));
}
static __device__ __forceinline__ uint32_t ldw(const float* p) {   // W: preconverted
    return __float_as_uint(*p);
}
static __device__ __forceinline__ void mma8(float c[4], const uint32_t a[4],
                                            const uint32_t b[2]) {
    asm volatile(
        "mma.sync.aligned.m16n8k8.row.col.f32.tf32.tf32.f32 "
        "{%0,%1,%2,%3},{%4,%5,%6,%7},{%8,%9},{%0,%1,%2,%3};"
        : "+f"(c[0]), "+f"(c[1]), "+f"(c[2]), "+f"(c[3])
        : "r"(a[0]), "r"(a[1]), "r"(a[2]), "r"(a[3]), "r"(b[0]), "r"(b[1]));
}
static __device__ __forceinline__ float sigf(float x) {
    return __fdividef(1.0f, 1.0f + __expf(-x));
}
static __device__ __forceinline__ float tanhff(float x) {
    float ax = fabsf(x), e = __expf(-2.0f * ax);
    return copysignf(__fdividef(1.0f - e, 1.0f + e), x);
}
static __device__ __forceinline__ float gru1(float rp, float zp, float ip,
                                             float hp, float hv) {
    float r = sigf(rp), z = sigf(zp);
    float n = tanhff(ip + r * hp);
    return n + z * (hv - n);
}

#define CP16(dst, src) \
    asm volatile("cp.async.cg.shared.global [%0], [%1], 16;" \
                 :: "r"(dst), "l"(src) : "memory")
#define CPC()  asm volatile("cp.async.commit_group;" ::: "memory")
#define CPW1() asm volatile("cp.async.wait_group 1;" ::: "memory")
#define CPW0() asm volatile("cp.async.wait_group 0;" ::: "memory")

__global__ void __launch_bounds__(256)
cvt_weights_kernel(const float* __restrict__ wih0, const float* __restrict__ whh0,
                   const float* __restrict__ wih1, const float* __restrict__ whh1)
{
    int i = blockIdx.x * 256 + threadIdx.x;          // float4 index
    if (i >= WSCR_TOTAL / 4) return;
    const float* src;
    int j = i * 4;
    if      (j < W1_OFF) src = wih0 + j;
    else if (j < W2_OFF) src = whh0 + (j - W1_OFF);
    else if (j < W3_OFF) src = wih1 + (j - W2_OFF);
    else                 src = whh1 + (j - W3_OFF);
    float4 v = *(const float4*)src;
    v.x = tf32r(v.x); v.y = tf32r(v.y); v.z = tf32r(v.z); v.w = tf32r(v.w);
    *(float4*)(w_scr + j) = v;
}

__global__ void __launch_bounds__(NT, 1)
gru_ac_kernel(const float* __restrict__ x,    const float* __restrict__ hin,
              const float* __restrict__ bih0, const float* __restrict__ bhh0,
              const float* __restrict__ bih1, const float* __restrict__ bhh1,
              const float* __restrict__ wp,   const float* __restrict__ bp,
              const float* __restrict__ wv,   const float* __restrict__ bv,
              float* __restrict__ out)
{
    extern __shared__ float sm[];
    const uint32_t smb = smem_u32(sm);
    const int tid  = threadIdx.x;
    const int lane = tid & 31;
    const int wid  = tid >> 5;
    const int wm   = wid >> 2;     // 0..3 : 32-row band
    const int wn   = wid & 3;      // 0..3 : 16-col band
    const int gID  = lane >> 2;
    const int tig  = lane & 3;
    const int rowbase = blockIdx.x * MT;

    float* outL  = out;
    float* outV  = out + (size_t)BATCH * ADIM;
    float* hbase = out + (size_t)BATCH * (ADIM + 1);   // [2][B][H]
    float* BIAS  = sm + BIAS_OFF;

    // staging slot geometry (float4 granularity)
    int ar[2], aj[2];
    #pragma unroll
    for (int i = 0; i < 2; ++i) {
        int s = tid + i * NT;           // 0..1023
        ar[i] = s >> 3; aj[i] = s & 7;  // A row 0..127
    }
    int wg[3], wl[3], wj[3];
    #pragma unroll
    for (int i = 0; i < 3; ++i) {
        int s = tid + i * NT;           // 0..1535
        int row = s >> 3;               // 0..191
        wg[i] = row >> 6; wl[i] = row & 63; wj[i] = s & 7;
    }

    for (int layer = 0; layer < 2; ++layer) {
        const float* wih = w_scr + (layer ? W2_OFF : W0_OFF);
        const float* whh = w_scr + (layer ? W3_OFF : W1_OFF);
        const float* bih = layer ? bih1 : bih0;
        const float* bhh = layer ? bhh1 : bhh0;
        const int    KX  = layer ? HDIM : IDIM;
        const int    ncx = KX >> 5;
        const int    nk  = ncx + (HDIM >> 5);
        const float* asrcx = layer ? (hbase + (size_t)rowbase * HDIM)
                                   : (x + (size_t)rowbase * IDIM);
        const int    axs   = layer ? HDIM : IDIM;
        const float* asrch = hin + (size_t)layer * BATCH * HDIM
                                 + (size_t)rowbase * HDIM;
        float*       hdst  = hbase + (size_t)layer * BATCH * HDIM
                                   + (size_t)rowbase * HDIM;

        // fused biases -> smem: [r | z | i_n | h_n] x 256
        #pragma unroll
        for (int it = 0; it < 2; ++it) {
            int i = tid + it * NT;
            int arr = i >> 8, c = i & 255;
            float v;
            if      (arr == 0) v = bih[c]       + bhh[c];
            else if (arr == 1) v = bih[256 + c] + bhh[256 + c];
            else if (arr == 2) v = bih[512 + c];
            else               v = bhh[512 + c];
            BIAS[i] = v;
        }

        for (int q = 0; q < 4; ++q) {
            const int qc = q * NC;

            auto prefetch = [&](int kc, int buf) {
                const bool isX = kc < ncx;
                const float* ab  = isX ? asrcx : asrch;
                const int    as_ = isX ? axs : HDIM;
                const float* wb  = isX ? wih : whh;
                const int    wk  = isX ? KX : HDIM;
                const int    ko  = (isX ? kc : kc - ncx) << 5;
                uint32_t Ab = smb + buf * (BUF_SZ * 4);
                uint32_t Wb = Ab + ASM_SZ * 4;
                #pragma unroll
                for (int i = 0; i < 2; ++i)
                    CP16(Ab + (ar[i] * AST + aj[i] * 4) * 4,
                         ab + (size_t)ar[i] * as_ + ko + aj[i] * 4);
                #pragma unroll
                for (int i = 0; i < 3; ++i)
                    CP16(Wb + ((wg[i] * 64 + wl[i]) * AST + wj[i] * 4) * 4,
                         wb + (size_t)(wg[i] * 256 + qc + wl[i]) * wk
                            + ko + wj[i] * 4);
                CPC();
            };

            float aR[2][2][4], aZ[2][2][4], aI[2][2][4], aH[2][2][4];
            #pragma unroll
            for (int t = 0; t < 2; ++t)
                #pragma unroll
                for (int s = 0; s < 2; ++s)
                    #pragma unroll
                    for (int k = 0; k < 4; ++k) {
                        aR[t][s][k] = 0.f; aZ[t][s][k] = 0.f;
                        aI[t][s][k] = 0.f; aH[t][s][k] = 0.f;
                    }

            prefetch(0, 0);
            prefetch(1, 1);

            for (int kc = 0; kc < nk; ++kc) {
                if (kc + 1 < nk) { CPW1(); } else { CPW0(); }
                __syncthreads();
                if (kc + 2 < nk) prefetch(kc + 2, (kc + 2) % 3);

                const float* Ab = sm + (kc % 3) * BUF_SZ;
                const float* Wb = Ab + ASM_SZ;
                const bool isX = kc < ncx;

                #pragma unroll
                for (int kk = 0; kk < 4; ++kk) {
                    uint32_t af[2][4];
                    #pragma unroll
                    for (int t = 0; t < 2; ++t) {
                        const float* ap = Ab + (wm * 32 + t * 16 + gID) * AST
                                             + kk * 8 + tig;
                        af[t][0] = lda(ap);
                        af[t][1] = lda(ap + 8 * AST);
                        af[t][2] = lda(ap + 4);
                        af[t][3] = lda(ap + 8 * AST + 4);
                    }
                    #pragma unroll
                    for (int s = 0; s < 2; ++s) {
                        const int nr = wn * 16 + s * 8 + gID;
                        const float* w0 = Wb + nr * AST + kk * 8 + tig;
                        uint32_t bR[2], bZ[2], bN[2];
                        bR[0] = ldw(w0);
                        bR[1] = ldw(w0 + 4);
                        bZ[0] = ldw(w0 + 64 * AST);
                        bZ[1] = ldw(w0 + 64 * AST + 4);
                        bN[0] = ldw(w0 + 128 * AST);
                        bN[1] = ldw(w0 + 128 * AST + 4);
                        #pragma unroll
                        for (int t = 0; t < 2; ++t) {
                            mma8(aR[t][s], af[t], bR);
                            mma8(aZ[t][s], af[t], bZ);
                        }
                        if (isX) {
                            #pragma unroll
                            for (int t = 0; t < 2; ++t) mma8(aI[t][s], af[t], bN);
                        } else {
                            #pragma unroll
                            for (int t = 0; t < 2; ++t) mma8(aH[t][s], af[t], bN);
                        }
                    }
                }
            }

            // elementwise GRU gates from fragments
            #pragma unroll
            for (int s = 0; s < 2; ++s) {
                const int c = qc + wn * 16 + s * 8 + tig * 2;
                float2 bRv = *(float2*)&BIAS[c];
                float2 bZv = *(float2*)&BIAS[256 + c];
                float2 bIv = *(float2*)&BIAS[512 + c];
                float2 bHv = *(float2*)&BIAS[768 + c];
                #pragma unroll
                for (int t = 0; t < 2; ++t) {
                    const int ra = wm * 32 + t * 16 + gID;
                    const int rb = ra + 8;
                    float2 ha = *(const float2*)&asrch[(size_t)ra * HDIM + c];
                    float2 hb = *(const float2*)&asrch[(size_t)rb * HDIM + c];
                    float2 oa, ob;
                    oa.x = gru1(aR[t][s][0] + bRv.x, aZ[t][s][0] + bZv.x,
                                aI[t][s][0] + bIv.x, aH[t][s][0] + bHv.x, ha.x);
                    oa.y = gru1(aR[t][s][1] + bRv.y, aZ[t][s][1] + bZv.y,
                                aI[t][s][1] + bIv.y, aH[t][s][1] + bHv.y, ha.y);
                    ob.x = gru1(aR[t][s][2] + bRv.x, aZ[t][s][2] + bZv.x,
                                aI[t][s][2] + bIv.x, aH[t][s][2] + bHv.x, hb.x);
                    ob.y = gru1(aR[t][s][3] + bRv.y, aZ[t][s][3] + bZv.y,
                                aI[t][s][3] + bIv.y, aH[t][s][3] + bHv.y, hb.y);
                    *(float2*)&hdst[(size_t)ra * HDIM + c] = oa;
                    *(float2*)&hdst[(size_t)rb * HDIM + c] = ob;
                }
            }
            __syncthreads();   // hdst visible; buffers/BIAS free for reuse
        }
    }

    // heads: logits = h1 @ w_p^T + b_p ; value = h1 @ w_v^T + b_v
    {
        const int row = tid >> 2;              // 0..127
        const int qq  = tid & 3;               // 8 logits per thread
        const float* h1r = hbase + (size_t)BATCH * HDIM
                                 + (size_t)(rowbase + row) * HDIM;
        float acc[8];
        #pragma unroll
        for (int a = 0; a < 8; ++a) acc[a] = bp[qq * 8 + a];
        float av = bv[0];
        const float4* h4 = (const float4*)h1r;
        for (int kb = 0; kb < HDIM / 4; ++kb) {
            float4 hv = h4[kb];
            #pragma unroll
            for (int a = 0; a < 8; ++a) {
                const float4 wq =
                    *(const float4*)&wp[(qq * 8 + a) * HDIM + kb * 4];
                acc[a] += hv.x * wq.x + hv.y * wq.y + hv.z * wq.z + hv.w * wq.w;
            }
            if (qq == 0) {
                const float4 wq = *(const float4*)&wv[kb * 4];
                av += hv.x * wq.x + hv.y * wq.y + hv.z * wq.z + hv.w * wq.w;
            }
        }
        #pragma unroll
        for (int a = 0; a < 8; ++a)
            outL[(size_t)(rowbase + row) * ADIM + qq * 8 + a] = acc[a];
        if (qq == 0) outV[rowbase + row] = av;
    }
}

extern "C" void kernel_launch(void* const* d_in, const int* in_sizes, int n_in,
                              void* d_out, int out_size) {
    const float* x    = (const float*)d_in[0];
    const float* hin  = (const float*)d_in[1];
    const float* wih0 = (const float*)d_in[2];
    const float* whh0 = (const float*)d_in[3];
    const float* bih0 = (const float*)d_in[4];
    const float* bhh0 = (const float*)d_in[5];
    const float* wih1 = (const float*)d_in[6];
    const float* whh1 = (const float*)d_in[7];
    const float* bih1 = (const float*)d_in[8];
    const float* bhh1 = (const float*)d_in[9];
    const float* wp   = (const float*)d_in[10];
    const float* bp   = (const float*)d_in[11];
    const float* wv   = (const float*)d_in[12];
    const float* bv   = (const float*)d_in[13];
    float* out = (float*)d_out;

    cvt_weights_kernel<<<(WSCR_TOTAL / 4 + 255) / 256, 256>>>(wih0, whh0, wih1, whh1);

    cudaFuncSetAttribute(gru_ac_kernel,
                         cudaFuncAttributeMaxDynamicSharedMemorySize, SMEM_DYN);
    gru_ac_kernel<<<NBLK, NT, SMEM_DYN>>>(x, hin, bih0, bhh0, bih1, bhh1,
                                          wp, bp, wv, bv, out);
}

// round 7
// speedup vs baseline: 1.2091x; 1.1363x over previous
#include <cuda_runtime.h>
#include <cstdint>

#define BATCH 32768
#define IDIM  128
#define HDIM  256
#define ADIM  32
#define MT    128
#define NT    512
#define NBLK  (BATCH/MT)

// ---- packed scratch (floats) ----
#define XPK   0u
#define H0PK  4194304u
#define H1PK  12582912u
#define W0X   20971520u
#define W0H   21069824u
#define W1X   21266432u
#define W1H   21463040u
#define SCR_TOTAL 21659648u
__device__ float scr[SCR_TOTAL];

#define SMS  260                       // smem row stride (floats)
#define SMEM_MAIN (128*SMS*4)          // 133120 B

static __device__ __forceinline__ float tf32r(float x) {
    float r; asm("cvt.rna.tf32.f32 %0, %1;" : "=f"(r) : "f"(x)); return r;
}
static __device__ __forceinline__ void mma8(float c[4], const uint32_t a[4],
                                            const uint32_t b[2]) {
    asm volatile(
        "mma.sync.aligned.m16n8k8.row.col.f32.tf32.tf32.f32 "
        "{%0,%1,%2,%3},{%4,%5,%6,%7},{%8,%9},{%0,%1,%2,%3};"
        : "+f"(c[0]), "+f"(c[1]), "+f"(c[2]), "+f"(c[3])
        : "r"(a[0]), "r"(a[1]), "r"(a[2]), "r"(a[3]), "r"(b[0]), "r"(b[1]));
}
static __device__ __forceinline__ float sigf(float x) {
    return __fdividef(1.0f, 1.0f + __expf(-x));
}
static __device__ __forceinline__ float tanhff(float x) {
    float ax = fabsf(x), e = __expf(-2.0f * ax);
    return copysignf(__fdividef(1.0f - e, 1.0f + e), x);
}
static __device__ __forceinline__ float gru1(float rp, float zp, float ip,
                                             float hp, float hv) {
    float r = sigf(rp), z = sigf(zp);
    float n = tanhff(ip + r * hp);
    return n + z * (hv - n);
}

// ---------------- pre-kernel: pack weights into fragment order ----------------
__global__ void __launch_bounds__(256)
pack_w(const float* __restrict__ wih0, const float* __restrict__ whh0,
       const float* __restrict__ wih1, const float* __restrict__ whh1)
{
    int i = blockIdx.x * 256 + threadIdx.x;     // global out float4 index
    if (i >= 172032) return;
    const float* src; uint32_t base; int K; int l = i;
    if (l < 24576)                { src = wih0; base = W0X; K = 128; }
    else if ((l -= 24576) < 49152){ src = whh0; base = W0H; K = 256; }
    else if ((l -= 49152) < 49152){ src = wih1; base = W1X; K = 256; }
    else { l -= 49152;              src = whh1; base = W1H; K = 256; }
    int lane = l & 31, blk = l >> 5;
    int KB2 = K >> 4;
    int j  = blk % KB2;
    int nb = (blk / KB2) & 31;
    int g  = blk / (KB2 * 32);
    int gid = lane >> 2, tg = lane & 3;
    int row = g * 256 + nb * 8 + gid;
    const float* wr = src + (size_t)row * K + j * 16 + tg;
    float4 v;
    v.x = tf32r(wr[0]); v.y = tf32r(wr[4]);
    v.z = tf32r(wr[8]); v.w = tf32r(wr[12]);
    ((float4*)(scr + base))[l] = v;
}

// ---------------- pre-kernel: pack A-sources into fragment order ----------------
__global__ void __launch_bounds__(256)
pack_a(const float* __restrict__ x, const float* __restrict__ hin)
{
    extern __shared__ float sb[];
    int bb = blockIdx.x, m = blockIdx.y, tid = threadIdx.x;
    const float* src; uint32_t base; int K;
    if (m == 0)      { src = x;   base = XPK;  K = IDIM; }
    else if (m == 1) { src = hin; base = H0PK; K = HDIM; }
    else             { src = hin + (size_t)BATCH * HDIM; base = H1PK; K = HDIM; }
    src += (size_t)bb * 128 * K;
    const int KQ = K / 4;
    for (int i = tid; i < 128 * KQ; i += 256) {
        int r = i / KQ, c = i % KQ;
        float4 v = ((const float4*)src)[i];
        *(float4*)&sb[r * SMS + c * 4] = v;
    }
    __syncthreads();
    const int KB = K / 8;
    const int nout = 8 * KB * 32;
    float4* outp = (float4*)(scr + base) + (size_t)bb * nout;
    for (int o = tid; o < nout; o += 256) {
        int lane = o & 31, kb = (o >> 5) % KB, mb = (o >> 5) / KB;
        int gid = lane >> 2, tg = lane & 3;
        int r0 = mb * 16 + gid, k = kb * 8 + tg;
        float4 v;
        v.x = tf32r(sb[r0 * SMS + k]);
        v.y = tf32r(sb[(r0 + 8) * SMS + k]);
        v.z = tf32r(sb[r0 * SMS + k + 4]);
        v.w = tf32r(sb[(r0 + 8) * SMS + k + 4]);
        outp[o] = v;
    }
}

#define FRAG(d, v) do { d[0] = __float_as_uint((v).x); d[1] = __float_as_uint((v).y); \
                        d[2] = __float_as_uint((v).z); d[3] = __float_as_uint((v).w); } while (0)

__global__ void __launch_bounds__(NT, 1)
gru_ac_kernel(const float* __restrict__ x,    const float* __restrict__ hin,
              const float* __restrict__ bih0, const float* __restrict__ bhh0,
              const float* __restrict__ bih1, const float* __restrict__ bhh1,
              const float* __restrict__ wp,   const float* __restrict__ bp,
              const float* __restrict__ wv,   const float* __restrict__ bv,
              float* __restrict__ out)
{
    extern __shared__ float h0s[];          // 128 x SMS (tf32 copy of h0)
    const float4* S4 = (const float4*)scr;
    const int tid  = threadIdx.x;
    const int lane = tid & 31;
    const int wid  = tid >> 5;
    const int wm   = wid >> 2;
    const int wn   = wid & 3;
    const int gID  = lane >> 2;
    const int tig  = lane & 3;
    const int bb   = blockIdx.x;
    const int rowbase = bb * MT;

    float* outL  = out;
    float* outV  = out + (size_t)BATCH * ADIM;
    float* hbase = out + (size_t)BATCH * (ADIM + 1);   // [2][B][H]

    for (int layer = 0; layer < 2; ++layer) {
        const float* bih = layer ? bih1 : bih0;
        const float* bhh = layer ? bhh1 : bhh0;
        const float* asrch = hin + (size_t)layer * BATCH * HDIM
                                 + (size_t)rowbase * HDIM;
        float* hdst = hbase + (size_t)layer * BATCH * HDIM
                            + (size_t)rowbase * HDIM;

        for (int q = 0; q < 4; ++q) {
            float aR[2][2][4], aZ[2][2][4], aI[2][2][4], aH[2][2][4];
            #pragma unroll
            for (int t = 0; t < 2; ++t)
                #pragma unroll
                for (int s = 0; s < 2; ++s)
                    #pragma unroll
                    for (int k = 0; k < 4; ++k) {
                        aR[t][s][k] = 0.f; aZ[t][s][k] = 0.f;
                        aI[t][s][k] = 0.f; aH[t][s][k] = 0.f;
                    }
            const int nb0 = q * 8 + wn * 2;

            // gmem-fragment phase: A from apk, W from wpk
            auto phase_pk = [&](uint32_t a_base4, int KB2a, uint32_t w_base4,
                                int KB2w, float (*accN)[2][4]) {
                const int KBa = KB2a * 2;
                uint32_t ia0 = a_base4 + (uint32_t)(bb * 8 + wm * 2) * KBa * 32 + lane;
                uint32_t ia1 = ia0 + KBa * 32;
                uint32_t iw[3][2];
                #pragma unroll
                for (int g = 0; g < 3; ++g)
                    #pragma unroll
                    for (int s = 0; s < 2; ++s)
                        iw[g][s] = w_base4
                            + (uint32_t)((g * 32 + nb0 + s) * KB2w) * 32 + lane;
                for (int j = 0; j < KB2a; ++j) {
                    float4 a00 = S4[ia0 + (2 * j) * 32];
                    float4 a01 = S4[ia0 + (2 * j + 1) * 32];
                    float4 a10 = S4[ia1 + (2 * j) * 32];
                    float4 a11 = S4[ia1 + (2 * j + 1) * 32];
                    float4 w_[3][2];
                    #pragma unroll
                    for (int g = 0; g < 3; ++g)
                        #pragma unroll
                        for (int s = 0; s < 2; ++s)
                            w_[g][s] = S4[iw[g][s] + j * 32];
                    uint32_t af[2][2][4];
                    FRAG(af[0][0], a00); FRAG(af[0][1], a01);
                    FRAG(af[1][0], a10); FRAG(af[1][1], a11);
                    #pragma unroll
                    for (int s = 0; s < 2; ++s) {
                        uint32_t bR[2][2], bZ[2][2], bN[2][2];
                        bR[0][0] = __float_as_uint(w_[0][s].x);
                        bR[0][1] = __float_as_uint(w_[0][s].y);
                        bR[1][0] = __float_as_uint(w_[0][s].z);
                        bR[1][1] = __float_as_uint(w_[0][s].w);
                        bZ[0][0] = __float_as_uint(w_[1][s].x);
                        bZ[0][1] = __float_as_uint(w_[1][s].y);
                        bZ[1][0] = __float_as_uint(w_[1][s].z);
                        bZ[1][1] = __float_as_uint(w_[1][s].w);
                        bN[0][0] = __float_as_uint(w_[2][s].x);
                        bN[0][1] = __float_as_uint(w_[2][s].y);
                        bN[1][0] = __float_as_uint(w_[2][s].z);
                        bN[1][1] = __float_as_uint(w_[2][s].w);
                        #pragma unroll
                        for (int h = 0; h < 2; ++h)
                            #pragma unroll
                            for (int t = 0; t < 2; ++t) {
                                mma8(aR[t][s], af[t][h], bR[h]);
                                mma8(aZ[t][s], af[t][h], bZ[h]);
                                mma8(accN[t][s], af[t][h], bN[h]);
                            }
                    }
                }
            };

            // smem-A phase (layer 1 x-part: A = tf32 h0 in smem)
            auto phase_sm = [&](uint32_t w_base4, float (*accN)[2][4]) {
                uint32_t iw[3][2];
                #pragma unroll
                for (int g = 0; g < 3; ++g)
                    #pragma unroll
                    for (int s = 0; s < 2; ++s)
                        iw[g][s] = w_base4
                            + (uint32_t)((g * 32 + nb0 + s) * 16) * 32 + lane;
                for (int j = 0; j < 16; ++j) {
                    uint32_t af[2][2][4];
                    #pragma unroll
                    for (int t = 0; t < 2; ++t) {
                        const float* hp = &h0s[(wm * 32 + t * 16 + gID) * SMS];
                        #pragma unroll
                        for (int h = 0; h < 2; ++h) {
                            int k = (2 * j + h) * 8 + tig;
                            af[t][h][0] = __float_as_uint(hp[k]);
                            af[t][h][1] = __float_as_uint(hp[8 * SMS + k]);
                            af[t][h][2] = __float_as_uint(hp[k + 4]);
                            af[t][h][3] = __float_as_uint(hp[8 * SMS + k + 4]);
                        }
                    }
                    float4 w_[3][2];
                    #pragma unroll
                    for (int g = 0; g < 3; ++g)
                        #pragma unroll
                        for (int s = 0; s < 2; ++s)
                            w_[g][s] = S4[iw[g][s] + j * 32];
                    #pragma unroll
                    for (int s = 0; s < 2; ++s) {
                        uint32_t bR[2][2], bZ[2][2], bN[2][2];
                        bR[0][0] = __float_as_uint(w_[0][s].x);
                        bR[0][1] = __float_as_uint(w_[0][s].y);
                        bR[1][0] = __float_as_uint(w_[0][s].z);
                        bR[1][1] = __float_as_uint(w_[0][s].w);
                        bZ[0][0] = __float_as_uint(w_[1][s].x);
                        bZ[0][1] = __float_as_uint(w_[1][s].y);
                        bZ[1][0] = __float_as_uint(w_[1][s].z);
                        bZ[1][1] = __float_as_uint(w_[1][s].w);
                        bN[0][0] = __float_as_uint(w_[2][s].x);
                        bN[0][1] = __float_as_uint(w_[2][s].y);
                        bN[1][0] = __float_as_uint(w_[2][s].z);
                        bN[1][1] = __float_as_uint(w_[2][s].w);
                        #pragma unroll
                        for (int h = 0; h < 2; ++h)
                            #pragma unroll
                            for (int t = 0; t < 2; ++t) {
                                mma8(aR[t][s], af[t][h], bR[h]);
                                mma8(aZ[t][s], af[t][h], bZ[h]);
                                mma8(accN[t][s], af[t][h], bN[h]);
                            }
                    }
                }
            };

            if (layer == 0) {
                phase_pk(XPK / 4,  8,  W0X / 4, 8,  aI);   // x part (K=128)
                phase_pk(H0PK / 4, 16, W0H / 4, 16, aH);   // h part (K=256)
            } else {
                phase_sm(W1X / 4, aI);                      // h0 (smem) part
                phase_pk(H1PK / 4, 16, W1H / 4, 16, aH);   // h part (K=256)
            }

            // ---- elementwise GRU gates ----
            #pragma unroll
            for (int s = 0; s < 2; ++s) {
                const int c = q * 64 + wn * 16 + s * 8 + tig * 2;
                float2 bi0 = *(const float2*)&bih[c];
                float2 bh0 = *(const float2*)&bhh[c];
                float2 bi1 = *(const float2*)&bih[256 + c];
                float2 bh1 = *(const float2*)&bhh[256 + c];
                float2 bIv = *(const float2*)&bih[512 + c];
                float2 bHv = *(const float2*)&bhh[512 + c];
                float2 bRv = make_float2(bi0.x + bh0.x, bi0.y + bh0.y);
                float2 bZv = make_float2(bi1.x + bh1.x, bi1.y + bh1.y);
                #pragma unroll
                for (int t = 0; t < 2; ++t) {
                    const int ra = wm * 32 + t * 16 + gID;
                    const int rb = ra + 8;
                    float2 ha = *(const float2*)&asrch[(size_t)ra * HDIM + c];
                    float2 hb = *(const float2*)&asrch[(size_t)rb * HDIM + c];
                    float2 oa, ob;
                    oa.x = gru1(aR[t][s][0] + bRv.x, aZ[t][s][0] + bZv.x,
                                aI[t][s][0] + bIv.x, aH[t][s][0] + bHv.x, ha.x);
                    oa.y = gru1(aR[t][s][1] + bRv.y, aZ[t][s][1] + bZv.y,
                                aI[t][s][1] + bIv.y, aH[t][s][1] + bHv.y, ha.y);
                    ob.x = gru1(aR[t][s][2] + bRv.x, aZ[t][s][2] + bZv.x,
                                aI[t][s][2] + bIv.x, aH[t][s][2] + bHv.x, hb.x);
                    ob.y = gru1(aR[t][s][3] + bRv.y, aZ[t][s][3] + bZv.y,
                                aI[t][s][3] + bIv.y, aH[t][s][3] + bHv.y, hb.y);
                    *(float2*)&hdst[(size_t)ra * HDIM + c] = oa;
                    *(float2*)&hdst[(size_t)rb * HDIM + c] = ob;
                    if (layer == 0) {
                        float2 ta = make_float2(tf32r(oa.x), tf32r(oa.y));
                        float2 tb = make_float2(tf32r(ob.x), tf32r(ob.y));
                        *(float2*)&h0s[ra * SMS + c] = ta;
                        *(float2*)&h0s[rb * SMS + c] = tb;
                    }
                }
            }
        }
        __syncthreads();   // h0s (and hdst) complete before layer 1 / heads
    }

    // heads: logits = h1 @ w_p^T + b_p ; value = h1 @ w_v^T + b_v
    {
        const int row = tid >> 2;
        const int qq  = tid & 3;
        const float* h1r = hbase + (size_t)BATCH * HDIM
                                 + (size_t)(rowbase + row) * HDIM;
        float acc[8];
        #pragma unroll
        for (int a = 0; a < 8; ++a) acc[a] = bp[qq * 8 + a];
        float av = bv[0];
        const float4* h4 = (const float4*)h1r;
        for (int kb = 0; kb < HDIM / 4; ++kb) {
            float4 hv = h4[kb];
            #pragma unroll
            for (int a = 0; a < 8; ++a) {
                const float4 wq =
                    *(const float4*)&wp[(qq * 8 + a) * HDIM + kb * 4];
                acc[a] += hv.x * wq.x + hv.y * wq.y + hv.z * wq.z + hv.w * wq.w;
            }
            if (qq == 0) {
                const float4 wq = *(const float4*)&wv[kb * 4];
                av += hv.x * wq.x + hv.y * wq.y + hv.z * wq.z + hv.w * wq.w;
            }
        }
        #pragma unroll
        for (int a = 0; a < 8; ++a)
            outL[(size_t)(rowbase + row) * ADIM + qq * 8 + a] = acc[a];
        if (qq == 0) outV[rowbase + row] = av;
    }
}

extern "C" void kernel_launch(void* const* d_in, const int* in_sizes, int n_in,
                              void* d_out, int out_size) {
    const float* x    = (const float*)d_in[0];
    const float* hin  = (const float*)d_in[1];
    const float* wih0 = (const float*)d_in[2];
    const float* whh0 = (const float*)d_in[3];
    const float* bih0 = (const float*)d_in[4];
    const float* bhh0 = (const float*)d_in[5];
    const float* wih1 = (const float*)d_in[6];
    const float* whh1 = (const float*)d_in[7];
    const float* bih1 = (const float*)d_in[8];
    const float* bhh1 = (const float*)d_in[9];
    const float* wp   = (const float*)d_in[10];
    const float* bp   = (const float*)d_in[11];
    const float* wv   = (const float*)d_in[12];
    const float* bv   = (const float*)d_in[13];
    float* out = (float*)d_out;

    pack_w<<<672, 256>>>(wih0, whh0, wih1, whh1);

    cudaFuncSetAttribute(pack_a,
                         cudaFuncAttributeMaxDynamicSharedMemorySize, SMEM_MAIN);
    pack_a<<<dim3(NBLK, 3), 256, SMEM_MAIN>>>(x, hin);

    cudaFuncSetAttribute(gru_ac_kernel,
                         cudaFuncAttributeMaxDynamicSharedMemorySize, SMEM_MAIN);
    gru_ac_kernel<<<NBLK, NT, SMEM_MAIN>>>(x, hin, bih0, bhh0, bih1, bhh1,
                                           wp, bp, wv, bv, out);
}